// round 8
// baseline (speedup 1.0000x reference)
#include <cuda_runtime.h>
#include <cuda_bf16.h>
#include <math_constants.h>

#define NNODES 100000
#define FIN 512
#define F1 16
#define F2P 8   // 7 padded to 8

// ---------------- scratch (no allocations allowed) ----------------
__device__ __align__(16) float g_dinv[NNODES];
__device__ __align__(16) float g_xw1[NNODES * F1];
__device__ __align__(16) float g_out1[NNODES * F1];
__device__ __align__(16) float g_xw2[NNODES * F2P];
__device__ __align__(16) float g_out2[NNODES * F2P];
__device__ int g_is64;   // edge_index dtype flag (1 = int64, 0 = int32)

// ---------------- edge access ----------------
// Layout: planar [all sources | all targets], E = element_count/2 entries per
// block (element count from in_sizes; dtype resolved by the device probe).
__device__ __forceinline__ void load_edge(const void* ei, int E, int e,
                                          int& r, int& c) {
    if (g_is64) {
        const long long* p = (const long long*)ei;
        r = (int)p[e];
        c = (int)p[(size_t)E + e];
    } else {
        const int* p = (const int*)ei;
        r = p[e];
        c = p[(size_t)E + e];
    }
}

// ---------------- kernels ----------------

// probe dtype: int64-view of int32 id pairs has a random-id hi word -> out of
// [0, n) almost surely at i=0; genuine int64 ids all lie in [0, n).
__global__ void k_detect(const void* ei, int n) {
    if (threadIdx.x != 0 || blockIdx.x != 0) return;
    const long long* p = (const long long*)ei;
    int ok = 1;
    for (int i = 0; i < 1024; i++) {
        long long v = p[i];
        if (v < 0 || v >= (long long)n) { ok = 0; break; }
    }
    g_is64 = ok;
}

__global__ void k_init_deg(int n) {
    int i = blockIdx.x * blockDim.x + threadIdx.x;
    if (i < n) g_dinv[i] = 1.0f;   // self-loop contributes 1
}

__global__ void k_deg(const void* __restrict__ ei, int E, int n) {
    int e = blockIdx.x * blockDim.x + threadIdx.x;
    if (e >= E) return;
    int r, c;
    load_edge(ei, E, e, r, c);
    if ((unsigned)c >= (unsigned)n) return;
    atomicAdd(&g_dinv[c], 1.0f);
}

__global__ void k_dinv(int n) {
    int i = blockIdx.x * blockDim.x + threadIdx.x;
    if (i < n) g_dinv[i] = rsqrtf(g_dinv[i]);
}

// xw1 = x @ W1. One thread per row; W1 staged in shared memory.
__global__ void __launch_bounds__(256) k_gemm1(const float* __restrict__ x,
                                               const float* __restrict__ W,
                                               int n) {
    __shared__ __align__(16) float sW[FIN * F1];  // 32 KB
    for (int i = threadIdx.x; i < FIN * F1; i += 256) sW[i] = W[i];
    __syncthreads();

    int row = blockIdx.x * 256 + threadIdx.x;
    if (row >= n) return;

    float acc[F1];
#pragma unroll
    for (int f = 0; f < F1; f++) acc[f] = 0.f;

    const float4* xr = (const float4*)(x + (size_t)row * FIN);
#pragma unroll 4
    for (int k4 = 0; k4 < FIN / 4; k4++) {
        float4 xv = xr[k4];
        const float* w0 = &sW[(k4 * 4 + 0) * F1];
        const float* w1 = &sW[(k4 * 4 + 1) * F1];
        const float* w2 = &sW[(k4 * 4 + 2) * F1];
        const float* w3 = &sW[(k4 * 4 + 3) * F1];
#pragma unroll
        for (int f = 0; f < F1; f++) {
            acc[f] += xv.x * w0[f];
            acc[f] += xv.y * w1[f];
            acc[f] += xv.z * w2[f];
            acc[f] += xv.w * w3[f];
        }
    }

    float4* o = (float4*)(g_xw1 + (size_t)row * F1);
#pragma unroll
    for (int q = 0; q < 4; q++)
        o[q] = make_float4(acc[q * 4], acc[q * 4 + 1], acc[q * 4 + 2], acc[q * 4 + 3]);
}

// out1 = b1 + dinv^2 * xw1   (analytic self-loop + bias)
__global__ void k_init1(const float* __restrict__ b1, int n) {
    int t = blockIdx.x * blockDim.x + threadIdx.x;
    if (t >= n * 4) return;
    int i = t >> 2, q = t & 3;
    float di = g_dinv[i];
    float s = di * di;
    float4 xw = *(const float4*)(g_xw1 + (size_t)i * F1 + q * 4);
    float4 o;
    o.x = b1[q * 4 + 0] + s * xw.x;
    o.y = b1[q * 4 + 1] + s * xw.y;
    o.z = b1[q * 4 + 2] + s * xw.z;
    o.w = b1[q * 4 + 3] + s * xw.w;
    *(float4*)(g_out1 + (size_t)i * F1 + q * 4) = o;
}

// layer-1 edge scatter: out1[col] += dinv[row]*dinv[col] * xw1[row]
__global__ void k_scatter1(const void* __restrict__ ei, int E, int n) {
    int e = blockIdx.x * blockDim.x + threadIdx.x;
    if (e >= E) return;
    int r, c;
    load_edge(ei, E, e, r, c);
    if ((unsigned)r >= (unsigned)n || (unsigned)c >= (unsigned)n) return;  // FIXED guard
    float norm = g_dinv[r] * g_dinv[c];
    const float4* src = (const float4*)(g_xw1 + (size_t)r * F1);
    float* dst = g_out1 + (size_t)c * F1;
#pragma unroll
    for (int j = 0; j < 4; j++) {
        float4 v = src[j];
        atomicAdd(dst + j * 4 + 0, norm * v.x);
        atomicAdd(dst + j * 4 + 1, norm * v.y);
        atomicAdd(dst + j * 4 + 2, norm * v.z);
        atomicAdd(dst + j * 4 + 3, norm * v.w);
    }
}

// h = relu(out1); xw2 = h @ W2 (7 cols, padded to 8 with zeros)
__global__ void k_layer2(const float* __restrict__ W2, int n) {
    int i = blockIdx.x * blockDim.x + threadIdx.x;
    if (i >= n) return;
    float h[16];
    const float4* p = (const float4*)(g_out1 + (size_t)i * F1);
#pragma unroll
    for (int q = 0; q < 4; q++) {
        float4 v = p[q];
        h[q * 4 + 0] = fmaxf(v.x, 0.f);
        h[q * 4 + 1] = fmaxf(v.y, 0.f);
        h[q * 4 + 2] = fmaxf(v.z, 0.f);
        h[q * 4 + 3] = fmaxf(v.w, 0.f);
    }
    float s[7] = {0.f, 0.f, 0.f, 0.f, 0.f, 0.f, 0.f};
#pragma unroll
    for (int k = 0; k < 16; k++) {
        float hk = h[k];
#pragma unroll
        for (int f = 0; f < 7; f++) s[f] += hk * __ldg(&W2[k * 7 + f]);
    }
    float* o = g_xw2 + (size_t)i * F2P;
#pragma unroll
    for (int f = 0; f < 7; f++) o[f] = s[f];
    o[7] = 0.f;
}

// out2 = b2 + dinv^2 * xw2
__global__ void k_init2(const float* __restrict__ b2, int n) {
    int i = blockIdx.x * blockDim.x + threadIdx.x;
    if (i >= n) return;
    float di = g_dinv[i];
    float s = di * di;
    float* o = g_out2 + (size_t)i * F2P;
    const float* xw = g_xw2 + (size_t)i * F2P;
#pragma unroll
    for (int f = 0; f < 7; f++) o[f] = b2[f] + s * xw[f];
    o[7] = 0.f;
}

// layer-2 edge scatter: 7 scalar atomics per edge
__global__ void k_scatter2(const void* __restrict__ ei, int E, int n) {
    int e = blockIdx.x * blockDim.x + threadIdx.x;
    if (e >= E) return;
    int r, c;
    load_edge(ei, E, e, r, c);
    if ((unsigned)r >= (unsigned)n || (unsigned)c >= (unsigned)n) return;  // FIXED guard
    float norm = g_dinv[r] * g_dinv[c];
    const float4* src = (const float4*)(g_xw2 + (size_t)r * F2P);
    float* dst = g_out2 + (size_t)c * F2P;
    float4 v0 = src[0], v1 = src[1];
    atomicAdd(dst + 0, norm * v0.x);
    atomicAdd(dst + 1, norm * v0.y);
    atomicAdd(dst + 2, norm * v0.z);
    atomicAdd(dst + 3, norm * v0.w);
    atomicAdd(dst + 4, norm * v1.x);
    atomicAdd(dst + 5, norm * v1.y);
    atomicAdd(dst + 6, norm * v1.z);
}

__global__ void k_logsoftmax(float* __restrict__ out, int n) {
    int i = blockIdx.x * blockDim.x + threadIdx.x;
    if (i >= n) return;
    const float* v = g_out2 + (size_t)i * F2P;
    float w[7];
    float m = -CUDART_INF_F;
#pragma unroll
    for (int f = 0; f < 7; f++) { w[f] = v[f]; m = fmaxf(m, w[f]); }
    float s = 0.f;
#pragma unroll
    for (int f = 0; f < 7; f++) s += expf(w[f] - m);
    float l = logf(s);
    float* o = out + (size_t)i * 7;
#pragma unroll
    for (int f = 0; f < 7; f++) o[f] = w[f] - m - l;
}

// ---------------- launch ----------------
// Inputs identified BY ELEMENT COUNT (x largest, edge_index second largest,
// W1=8192, W2=112, b1=16, b2=7); positional fallback otherwise.
extern "C" void kernel_launch(void* const* d_in, const int* in_sizes, int n_in,
                              void* d_out, int out_size) {
    const void* x  = d_in[0];
    const void* ei = d_in[1];
    const void* W1 = d_in[2];
    const void* b1 = d_in[3];
    const void* W2 = d_in[4];
    const void* b2 = d_in[5];
    int x_sz = in_sizes[0], e_sz = in_sizes[1];

    if (n_in >= 6) {
        int ix = 0;
        for (int i = 1; i < n_in; i++) if (in_sizes[i] > in_sizes[ix]) ix = i;
        int ie = (ix == 0) ? 1 : 0;
        for (int i = 0; i < n_in; i++)
            if (i != ix && in_sizes[i] > in_sizes[ie]) ie = i;
        x = d_in[ix]; x_sz = in_sizes[ix];
        ei = d_in[ie]; e_sz = in_sizes[ie];
        for (int i = 0; i < n_in; i++) {
            if (i == ix || i == ie) continue;
            switch (in_sizes[i]) {
                case 8192: W1 = d_in[i]; break;   // 512*16
                case 112:  W2 = d_in[i]; break;   // 16*7
                case 16:   b1 = d_in[i]; break;
                case 7:    b2 = d_in[i]; break;
                default: break;
            }
        }
    }

    int n = x_sz / FIN;   // 100000
    int E = e_sz / 2;     // 3200000 edges (planar [src | dst])

    const int T = 256;
    int gbN  = (n + T - 1) / T;
    int gbE  = (E + T - 1) / T;
    int gbN4 = (n * 4 + T - 1) / T;

    k_detect<<<1, 32>>>(ei, n);
    k_init_deg<<<gbN, T>>>(n);
    k_deg<<<gbE, T>>>(ei, E, n);
    k_dinv<<<gbN, T>>>(n);
    k_gemm1<<<gbN, T>>>((const float*)x, (const float*)W1, n);
    k_init1<<<gbN4, T>>>((const float*)b1, n);
    k_scatter1<<<gbE, T>>>(ei, E, n);
    k_layer2<<<gbN, T>>>((const float*)W2, n);
    k_init2<<<gbN, T>>>((const float*)b2, n);
    k_scatter2<<<gbE, T>>>(ei, E, n);
    k_logsoftmax<<<gbN, T>>>((float*)d_out, n);
}

// round 9
// speedup vs baseline: 1.6805x; 1.6805x over previous
#include <cuda_runtime.h>
#include <cuda_bf16.h>
#include <math_constants.h>

#define NNODES 100000
#define FIN 512
#define F1 16
#define F2P 8   // 7 padded to 8

// ---------------- scratch (no allocations allowed) ----------------
__device__ __align__(16) float g_dinv[NNODES];
__device__ __align__(16) float g_xw1[NNODES * F1];
__device__ __align__(16) float g_out1[NNODES * F1];
__device__ __align__(16) float g_xw2[NNODES * F2P];
__device__ __align__(16) float g_out2[NNODES * F2P];
__device__ int g_is64;   // edge_index dtype flag (1 = int64, 0 = int32)

// ---------------- helpers ----------------
// Vector reduction: 1 RED op moves 16 bytes (4x fewer LTS atomic ops than
// scalar atomicAdd). dst must be 16B-aligned (all our arrays are).
__device__ __forceinline__ void red_v4(float* p, float a, float b, float c, float d) {
    asm volatile("red.global.add.v4.f32 [%0], {%1, %2, %3, %4};"
                 :: "l"(p), "f"(a), "f"(b), "f"(c), "f"(d) : "memory");
}

// Layout: planar [all sources | all targets], E entries per block.
__device__ __forceinline__ void load_edge(const void* ei, int E, int e,
                                          int& r, int& c) {
    if (g_is64) {
        const long long* p = (const long long*)ei;
        r = (int)p[e];
        c = (int)p[(size_t)E + e];
    } else {
        const int* p = (const int*)ei;
        r = p[e];
        c = p[(size_t)E + e];
    }
}

// ---------------- kernels ----------------

// probe dtype: int64-view of int32 id pairs has a random-id hi word -> out of
// [0, n) almost surely at i=0; genuine int64 ids all lie in [0, n).
__global__ void k_detect(const void* ei, int n) {
    if (threadIdx.x != 0 || blockIdx.x != 0) return;
    const long long* p = (const long long*)ei;
    int ok = 1;
    for (int i = 0; i < 1024; i++) {
        long long v = p[i];
        if (v < 0 || v >= (long long)n) { ok = 0; break; }
    }
    g_is64 = ok;
}

__global__ void k_init_deg(int n) {
    int i = blockIdx.x * blockDim.x + threadIdx.x;
    if (i < n) g_dinv[i] = 1.0f;   // self-loop contributes 1
}

__global__ void k_deg(const void* __restrict__ ei, int E, int n) {
    int e = blockIdx.x * blockDim.x + threadIdx.x;
    if (e >= E) return;
    int r, c;
    load_edge(ei, E, e, r, c);
    if ((unsigned)c >= (unsigned)n) return;
    atomicAdd(&g_dinv[c], 1.0f);
}

__global__ void k_dinv(int n) {
    int i = blockIdx.x * blockDim.x + threadIdx.x;
    if (i < n) g_dinv[i] = rsqrtf(g_dinv[i]);
}

// xw1 = x @ W1. One thread per row; W1 staged in shared memory.
__global__ void __launch_bounds__(256) k_gemm1(const float* __restrict__ x,
                                               const float* __restrict__ W,
                                               int n) {
    __shared__ __align__(16) float sW[FIN * F1];  // 32 KB
    for (int i = threadIdx.x; i < FIN * F1; i += 256) sW[i] = W[i];
    __syncthreads();

    int row = blockIdx.x * 256 + threadIdx.x;
    if (row >= n) return;

    float acc[F1];
#pragma unroll
    for (int f = 0; f < F1; f++) acc[f] = 0.f;

    const float4* xr = (const float4*)(x + (size_t)row * FIN);
#pragma unroll 4
    for (int k4 = 0; k4 < FIN / 4; k4++) {
        float4 xv = xr[k4];
        const float* w0 = &sW[(k4 * 4 + 0) * F1];
        const float* w1 = &sW[(k4 * 4 + 1) * F1];
        const float* w2 = &sW[(k4 * 4 + 2) * F1];
        const float* w3 = &sW[(k4 * 4 + 3) * F1];
#pragma unroll
        for (int f = 0; f < F1; f++) {
            acc[f] += xv.x * w0[f];
            acc[f] += xv.y * w1[f];
            acc[f] += xv.z * w2[f];
            acc[f] += xv.w * w3[f];
        }
    }

    float4* o = (float4*)(g_xw1 + (size_t)row * F1);
#pragma unroll
    for (int q = 0; q < 4; q++)
        o[q] = make_float4(acc[q * 4], acc[q * 4 + 1], acc[q * 4 + 2], acc[q * 4 + 3]);
}

// out1 = b1 + dinv^2 * xw1   (analytic self-loop + bias)
__global__ void k_init1(const float* __restrict__ b1, int n) {
    int t = blockIdx.x * blockDim.x + threadIdx.x;
    if (t >= n * 4) return;
    int i = t >> 2, q = t & 3;
    float di = g_dinv[i];
    float s = di * di;
    float4 xw = *(const float4*)(g_xw1 + (size_t)i * F1 + q * 4);
    float4 o;
    o.x = b1[q * 4 + 0] + s * xw.x;
    o.y = b1[q * 4 + 1] + s * xw.y;
    o.z = b1[q * 4 + 2] + s * xw.z;
    o.w = b1[q * 4 + 3] + s * xw.w;
    *(float4*)(g_out1 + (size_t)i * F1 + q * 4) = o;
}

// layer-1 edge scatter: out1[col] += dinv[row]*dinv[col] * xw1[row]
// 4 vector REDs per edge (16 floats).
__global__ void k_scatter1(const void* __restrict__ ei, int E, int n) {
    int e = blockIdx.x * blockDim.x + threadIdx.x;
    if (e >= E) return;
    int r, c;
    load_edge(ei, E, e, r, c);
    if ((unsigned)r >= (unsigned)n || (unsigned)c >= (unsigned)n) return;
    float norm = g_dinv[r] * g_dinv[c];
    const float4* src = (const float4*)(g_xw1 + (size_t)r * F1);
    float* dst = g_out1 + (size_t)c * F1;
#pragma unroll
    for (int j = 0; j < 4; j++) {
        float4 v = src[j];
        red_v4(dst + j * 4, norm * v.x, norm * v.y, norm * v.z, norm * v.w);
    }
}

// h = relu(out1); xw2 = h @ W2 (7 cols, padded to 8 with zeros)
__global__ void k_layer2(const float* __restrict__ W2, int n) {
    int i = blockIdx.x * blockDim.x + threadIdx.x;
    if (i >= n) return;
    float h[16];
    const float4* p = (const float4*)(g_out1 + (size_t)i * F1);
#pragma unroll
    for (int q = 0; q < 4; q++) {
        float4 v = p[q];
        h[q * 4 + 0] = fmaxf(v.x, 0.f);
        h[q * 4 + 1] = fmaxf(v.y, 0.f);
        h[q * 4 + 2] = fmaxf(v.z, 0.f);
        h[q * 4 + 3] = fmaxf(v.w, 0.f);
    }
    float s[8] = {0.f, 0.f, 0.f, 0.f, 0.f, 0.f, 0.f, 0.f};
#pragma unroll
    for (int k = 0; k < 16; k++) {
        float hk = h[k];
#pragma unroll
        for (int f = 0; f < 7; f++) s[f] += hk * __ldg(&W2[k * 7 + f]);
    }
    float4* o = (float4*)(g_xw2 + (size_t)i * F2P);
    o[0] = make_float4(s[0], s[1], s[2], s[3]);
    o[1] = make_float4(s[4], s[5], s[6], 0.f);
}

// out2 = b2 + dinv^2 * xw2
__global__ void k_init2(const float* __restrict__ b2, int n) {
    int i = blockIdx.x * blockDim.x + threadIdx.x;
    if (i >= n) return;
    float di = g_dinv[i];
    float s = di * di;
    const float4* xw = (const float4*)(g_xw2 + (size_t)i * F2P);
    float4 v0 = xw[0], v1 = xw[1];
    float4* o = (float4*)(g_out2 + (size_t)i * F2P);
    o[0] = make_float4(b2[0] + s * v0.x, b2[1] + s * v0.y,
                       b2[2] + s * v0.z, b2[3] + s * v0.w);
    o[1] = make_float4(b2[4] + s * v1.x, b2[5] + s * v1.y,
                       b2[6] + s * v1.z, 0.f);
}

// layer-2 edge scatter: 2 vector REDs per edge (8 floats, pad lane = +0)
__global__ void k_scatter2(const void* __restrict__ ei, int E, int n) {
    int e = blockIdx.x * blockDim.x + threadIdx.x;
    if (e >= E) return;
    int r, c;
    load_edge(ei, E, e, r, c);
    if ((unsigned)r >= (unsigned)n || (unsigned)c >= (unsigned)n) return;
    float norm = g_dinv[r] * g_dinv[c];
    const float4* src = (const float4*)(g_xw2 + (size_t)r * F2P);
    float* dst = g_out2 + (size_t)c * F2P;
    float4 v0 = src[0], v1 = src[1];
    red_v4(dst,     norm * v0.x, norm * v0.y, norm * v0.z, norm * v0.w);
    red_v4(dst + 4, norm * v1.x, norm * v1.y, norm * v1.z, 0.f);
}

__global__ void k_logsoftmax(float* __restrict__ out, int n) {
    int i = blockIdx.x * blockDim.x + threadIdx.x;
    if (i >= n) return;
    const float* v = g_out2 + (size_t)i * F2P;
    float w[7];
    float m = -CUDART_INF_F;
#pragma unroll
    for (int f = 0; f < 7; f++) { w[f] = v[f]; m = fmaxf(m, w[f]); }
    float s = 0.f;
#pragma unroll
    for (int f = 0; f < 7; f++) s += expf(w[f] - m);
    float l = logf(s);
    float* o = out + (size_t)i * 7;
#pragma unroll
    for (int f = 0; f < 7; f++) o[f] = w[f] - m - l;
}

// ---------------- launch ----------------
// Inputs identified BY ELEMENT COUNT (x largest, edge_index second largest,
// W1=8192, W2=112, b1=16, b2=7); positional fallback otherwise.
extern "C" void kernel_launch(void* const* d_in, const int* in_sizes, int n_in,
                              void* d_out, int out_size) {
    const void* x  = d_in[0];
    const void* ei = d_in[1];
    const void* W1 = d_in[2];
    const void* b1 = d_in[3];
    const void* W2 = d_in[4];
    const void* b2 = d_in[5];
    int x_sz = in_sizes[0], e_sz = in_sizes[1];

    if (n_in >= 6) {
        int ix = 0;
        for (int i = 1; i < n_in; i++) if (in_sizes[i] > in_sizes[ix]) ix = i;
        int ie = (ix == 0) ? 1 : 0;
        for (int i = 0; i < n_in; i++)
            if (i != ix && in_sizes[i] > in_sizes[ie]) ie = i;
        x = d_in[ix]; x_sz = in_sizes[ix];
        ei = d_in[ie]; e_sz = in_sizes[ie];
        for (int i = 0; i < n_in; i++) {
            if (i == ix || i == ie) continue;
            switch (in_sizes[i]) {
                case 8192: W1 = d_in[i]; break;   // 512*16
                case 112:  W2 = d_in[i]; break;   // 16*7
                case 16:   b1 = d_in[i]; break;
                case 7:    b2 = d_in[i]; break;
                default: break;
            }
        }
    }

    int n = x_sz / FIN;   // 100000
    int E = e_sz / 2;     // 3200000 edges (planar [src | dst])

    const int T = 256;
    int gbN  = (n + T - 1) / T;
    int gbE  = (E + T - 1) / T;
    int gbN4 = (n * 4 + T - 1) / T;

    k_detect<<<1, 32>>>(ei, n);
    k_init_deg<<<gbN, T>>>(n);
    k_deg<<<gbE, T>>>(ei, E, n);
    k_dinv<<<gbN, T>>>(n);
    k_gemm1<<<gbN, T>>>((const float*)x, (const float*)W1, n);
    k_init1<<<gbN4, T>>>((const float*)b1, n);
    k_scatter1<<<gbE, T>>>(ei, E, n);
    k_layer2<<<gbN, T>>>((const float*)W2, n);
    k_init2<<<gbN, T>>>((const float*)b2, n);
    k_scatter2<<<gbE, T>>>(ei, E, n);
    k_logsoftmax<<<gbN, T>>>((float*)d_out, n);
}

// round 11
// speedup vs baseline: 1.9227x; 1.1442x over previous
#include <cuda_runtime.h>
#include <cuda_bf16.h>
#include <math_constants.h>

#define NNODES 100000
#define FIN 512
#define F1 16
#define F2P 8   // 7 padded to 8

// ---------------- scratch (no allocations allowed) ----------------
__device__ __align__(16) float g_dinv[NNODES];
__device__ __align__(16) float g_y1[NNODES * F1];    // dinv[r] * xw1[r]  (gather src)
__device__ __align__(16) float g_acc1[NNODES * F1];  // y1[c] + sum y1[r] (scatter dst)
__device__ __align__(16) float g_y2[NNODES * F2P];
__device__ __align__(16) float g_acc2[NNODES * F2P];
__device__ int g_is64;   // edge_index dtype flag (1 = int64, 0 = int32)

// ---------------- helpers ----------------
__device__ __forceinline__ void red_v4(float* p, float a, float b, float c, float d) {
    asm volatile("red.global.add.v4.f32 [%0], {%1, %2, %3, %4};"
                 :: "l"(p), "f"(a), "f"(b), "f"(c), "f"(d) : "memory");
}
__device__ __forceinline__ unsigned long long fma2(unsigned long long a,
                                                   unsigned long long b,
                                                   unsigned long long c) {
    unsigned long long d;
    asm("fma.rn.f32x2 %0, %1, %2, %3;" : "=l"(d) : "l"(a), "l"(b), "l"(c));
    return d;
}
__device__ __forceinline__ unsigned long long mul2(unsigned long long a,
                                                   unsigned long long b) {
    unsigned long long d;
    asm("mul.rn.f32x2 %0, %1, %2;" : "=l"(d) : "l"(a), "l"(b));
    return d;
}
__device__ __forceinline__ unsigned long long pack2(float x) {
    unsigned long long d;
    unsigned xi = __float_as_uint(x);
    asm("mov.b64 %0, {%1, %1};" : "=l"(d) : "r"(xi));
    return d;
}

// Layout: planar [all sources | all targets], E entries per block.
__device__ __forceinline__ void load_edge(const void* ei, int E, int e,
                                          int& r, int& c) {
    if (g_is64) {
        const long long* p = (const long long*)ei;
        r = (int)p[e];
        c = (int)p[(size_t)E + e];
    } else {
        const int* p = (const int*)ei;
        r = p[e];
        c = p[(size_t)E + e];
    }
}
__device__ __forceinline__ int load_col(const void* ei, int E, int e) {
    if (g_is64) return (int)((const long long*)ei)[(size_t)E + e];
    return ((const int*)ei)[(size_t)E + e];
}

// ---------------- kernels ----------------

// probe dtype: int64-view of int32 id pairs has a random-id hi word.
__global__ void k_detect(const void* ei, int n) {
    if (threadIdx.x != 0 || blockIdx.x != 0) return;
    const long long* p = (const long long*)ei;
    int ok = 1;
    for (int i = 0; i < 1024; i++) {
        long long v = p[i];
        if (v < 0 || v >= (long long)n) { ok = 0; break; }
    }
    g_is64 = ok;
}

__global__ void k_init_deg(int n) {
    int i = blockIdx.x * blockDim.x + threadIdx.x;
    if (i < n) g_dinv[i] = 1.0f;   // self-loop contributes 1
}

__global__ void k_deg(const void* __restrict__ ei, int E, int n) {
    int e = blockIdx.x * blockDim.x + threadIdx.x;
    if (e >= E) return;
    int c = load_col(ei, E, e);
    if ((unsigned)c >= (unsigned)n) return;
    atomicAdd(&g_dinv[c], 1.0f);
}

__global__ void k_dinv(int n) {
    int i = blockIdx.x * blockDim.x + threadIdx.x;
    if (i < n) g_dinv[i] = rsqrtf(g_dinv[i]);
}

// y1 = dinv[row] * (x @ W1), written to BOTH g_y1 (gather source) and
// g_acc1 (accumulator init = self-loop term).
// Packed f32x2 math: W1 staged in smem as f32-pair u64s; per k step:
// 4x LDS.128 + 8x FMA2 (vs 16 LDS.32 + 16 FFMA scalar).
__global__ void __launch_bounds__(256) k_gemm1(const float* __restrict__ x,
                                               const float* __restrict__ W,
                                               int n) {
    __shared__ __align__(16) unsigned long long sW[FIN * 8];  // 32 KB
    {
        const ulonglong2* Wv = (const ulonglong2*)W;
        ulonglong2* sWv = (ulonglong2*)sW;
        // FIN*F1 floats = FIN*8 u64 = FIN*4 ulonglong2 (2048) -- FIXED bound
        for (int i = threadIdx.x; i < FIN * 4; i += 256) sWv[i] = Wv[i];
    }
    __syncthreads();

    int row = blockIdx.x * 256 + threadIdx.x;
    if (row >= n) return;

    unsigned long long acc[8];
#pragma unroll
    for (int f = 0; f < 8; f++) acc[f] = 0ull;

    const float4* xr = (const float4*)(x + (size_t)row * FIN);
#pragma unroll 2
    for (int k4 = 0; k4 < FIN / 4; k4++) {
        float4 xv = xr[k4];
#pragma unroll
        for (int d = 0; d < 4; d++) {
            float xk = (d == 0) ? xv.x : (d == 1) ? xv.y : (d == 2) ? xv.z : xv.w;
            unsigned long long xx = pack2(xk);
            const ulonglong2* wp = (const ulonglong2*)&sW[(k4 * 4 + d) * 8];
            ulonglong2 wa = wp[0], wb = wp[1];
            acc[0] = fma2(xx, wa.x, acc[0]);
            acc[1] = fma2(xx, wa.y, acc[1]);
            acc[2] = fma2(xx, wb.x, acc[2]);
            acc[3] = fma2(xx, wb.y, acc[3]);
            ulonglong2 wc = wp[2], wd = wp[3];
            acc[4] = fma2(xx, wc.x, acc[4]);
            acc[5] = fma2(xx, wc.y, acc[5]);
            acc[6] = fma2(xx, wd.x, acc[6]);
            acc[7] = fma2(xx, wd.y, acc[7]);
        }
    }

    // y = dinv[row] * acc  (packed multiply), dual store
    unsigned long long dd = pack2(g_dinv[row]);
    ulonglong2* o1 = (ulonglong2*)(g_y1 + (size_t)row * F1);
    ulonglong2* o2 = (ulonglong2*)(g_acc1 + (size_t)row * F1);
#pragma unroll
    for (int q = 0; q < 4; q++) {
        ulonglong2 v;
        v.x = mul2(acc[q * 2 + 0], dd);
        v.y = mul2(acc[q * 2 + 1], dd);
        o1[q] = v;
        o2[q] = v;
    }
}

// layer-1 edge scatter: acc1[c] += y1[r]   (pure gather + vector RED)
__global__ void k_scatter1(const void* __restrict__ ei, int E, int n) {
    int e = blockIdx.x * blockDim.x + threadIdx.x;
    if (e >= E) return;
    int r, c;
    load_edge(ei, E, e, r, c);
    if ((unsigned)r >= (unsigned)n || (unsigned)c >= (unsigned)n) return;
    const float4* src = (const float4*)(g_y1 + (size_t)r * F1);
    float* dst = g_acc1 + (size_t)c * F1;
#pragma unroll
    for (int j = 0; j < 4; j++) {
        float4 v = src[j];
        red_v4(dst + j * 4, v.x, v.y, v.z, v.w);
    }
}

// h = relu(b1 + dinv[i]*acc1[i]); y2 = dinv[i]*(h @ W2); dual store.
__global__ void k_layer2(const float* __restrict__ W2,
                         const float* __restrict__ b1, int n) {
    int i = blockIdx.x * blockDim.x + threadIdx.x;
    if (i >= n) return;
    float di = g_dinv[i];
    float h[16];
    const float4* p = (const float4*)(g_acc1 + (size_t)i * F1);
#pragma unroll
    for (int q = 0; q < 4; q++) {
        float4 v = p[q];
        h[q * 4 + 0] = fmaxf(__ldg(&b1[q * 4 + 0]) + di * v.x, 0.f);
        h[q * 4 + 1] = fmaxf(__ldg(&b1[q * 4 + 1]) + di * v.y, 0.f);
        h[q * 4 + 2] = fmaxf(__ldg(&b1[q * 4 + 2]) + di * v.z, 0.f);
        h[q * 4 + 3] = fmaxf(__ldg(&b1[q * 4 + 3]) + di * v.w, 0.f);
    }
    float s[7] = {0.f, 0.f, 0.f, 0.f, 0.f, 0.f, 0.f};
#pragma unroll
    for (int k = 0; k < 16; k++) {
        float hk = h[k];
#pragma unroll
        for (int f = 0; f < 7; f++) s[f] += hk * __ldg(&W2[k * 7 + f]);
    }
    float4 v0 = make_float4(di * s[0], di * s[1], di * s[2], di * s[3]);
    float4 v1 = make_float4(di * s[4], di * s[5], di * s[6], 0.f);
    float4* oy = (float4*)(g_y2 + (size_t)i * F2P);
    float4* oa = (float4*)(g_acc2 + (size_t)i * F2P);
    oy[0] = v0; oy[1] = v1;
    oa[0] = v0; oa[1] = v1;
}

// layer-2 edge scatter: acc2[c] += y2[r]   (2 vector REDs)
__global__ void k_scatter2(const void* __restrict__ ei, int E, int n) {
    int e = blockIdx.x * blockDim.x + threadIdx.x;
    if (e >= E) return;
    int r, c;
    load_edge(ei, E, e, r, c);
    if ((unsigned)r >= (unsigned)n || (unsigned)c >= (unsigned)n) return;
    const float4* src = (const float4*)(g_y2 + (size_t)r * F2P);
    float* dst = g_acc2 + (size_t)c * F2P;
    float4 v0 = src[0], v1 = src[1];
    red_v4(dst,     v0.x, v0.y, v0.z, v0.w);
    red_v4(dst + 4, v1.x, v1.y, v1.z, 0.f);
}

// w = b2 + dinv[i]*acc2[i]; log_softmax
__global__ void k_logsoftmax(const float* __restrict__ b2,
                             float* __restrict__ out, int n) {
    int i = blockIdx.x * blockDim.x + threadIdx.x;
    if (i >= n) return;
    float di = g_dinv[i];
    const float4* p = (const float4*)(g_acc2 + (size_t)i * F2P);
    float4 a0 = p[0], a1 = p[1];
    float w[7];
    w[0] = __ldg(&b2[0]) + di * a0.x;
    w[1] = __ldg(&b2[1]) + di * a0.y;
    w[2] = __ldg(&b2[2]) + di * a0.z;
    w[3] = __ldg(&b2[3]) + di * a0.w;
    w[4] = __ldg(&b2[4]) + di * a1.x;
    w[5] = __ldg(&b2[5]) + di * a1.y;
    w[6] = __ldg(&b2[6]) + di * a1.z;
    float m = w[0];
#pragma unroll
    for (int f = 1; f < 7; f++) m = fmaxf(m, w[f]);
    float s = 0.f;
#pragma unroll
    for (int f = 0; f < 7; f++) s += expf(w[f] - m);
    float l = logf(s);
    float* o = out + (size_t)i * 7;
#pragma unroll
    for (int f = 0; f < 7; f++) o[f] = w[f] - m - l;
}

// ---------------- launch ----------------
// Inputs identified BY ELEMENT COUNT (x largest, edge_index second largest,
// W1=8192, W2=112, b1=16, b2=7); positional fallback otherwise.
extern "C" void kernel_launch(void* const* d_in, const int* in_sizes, int n_in,
                              void* d_out, int out_size) {
    const void* x  = d_in[0];
    const void* ei = d_in[1];
    const void* W1 = d_in[2];
    const void* b1 = d_in[3];
    const void* W2 = d_in[4];
    const void* b2 = d_in[5];
    int x_sz = in_sizes[0], e_sz = in_sizes[1];

    if (n_in >= 6) {
        int ix = 0;
        for (int i = 1; i < n_in; i++) if (in_sizes[i] > in_sizes[ix]) ix = i;
        int ie = (ix == 0) ? 1 : 0;
        for (int i = 0; i < n_in; i++)
            if (i != ix && in_sizes[i] > in_sizes[ie]) ie = i;
        x = d_in[ix]; x_sz = in_sizes[ix];
        ei = d_in[ie]; e_sz = in_sizes[ie];
        for (int i = 0; i < n_in; i++) {
            if (i == ix || i == ie) continue;
            switch (in_sizes[i]) {
                case 8192: W1 = d_in[i]; break;   // 512*16
                case 112:  W2 = d_in[i]; break;   // 16*7
                case 16:   b1 = d_in[i]; break;
                case 7:    b2 = d_in[i]; break;
                default: break;
            }
        }
    }

    int n = x_sz / FIN;   // 100000
    int E = e_sz / 2;     // 3200000 edges (planar [src | dst])

    const int T = 256;
    int gbN = (n + T - 1) / T;
    int gbE = (E + T - 1) / T;

    k_detect<<<1, 32>>>(ei, n);
    k_init_deg<<<gbN, T>>>(n);
    k_deg<<<gbE, T>>>(ei, E, n);
    k_dinv<<<gbN, T>>>(n);
    k_gemm1<<<gbN, T>>>((const float*)x, (const float*)W1, n);
    k_scatter1<<<gbE, T>>>(ei, E, n);
    k_layer2<<<gbN, T>>>((const float*)W2, (const float*)b1, n);
    k_scatter2<<<gbE, T>>>(ei, E, n);
    k_logsoftmax<<<gbN, T>>>((const float*)b2, (float*)d_out, n);
}